// round 5
// baseline (speedup 1.0000x reference)
#include <cuda_runtime.h>
#include <cuda_bf16.h>

// Problem constants
#define C_IN  64
#define C_OUT 64
#define XD 32
#define XH 64
#define XW 64
#define OD 64
#define OH 128
#define OW 128
#define ZD 68
#define ZH 132
#define ZW 132

#define X_CH_STRIDE (XD*XH*XW)      // 131072
#define O_CH_STRIDE (OD*OH*OW)      // 1048576

#define NUM_BLOCKS 4096             // 32 d' * 64 h' * 2 half-planes

__device__ __forceinline__
void copy_rows(const float* __restrict__ z, float* __restrict__ out,
               int r0, int lane)
{
    // 8 rows, unroll 4 for MLP. out[64+c, d, h, :] = z[c, d+2, h+2, 2:130]
    #pragma unroll
    for (int jj = 0; jj < 8; jj += 4) {
        float4 v[4];
        #pragma unroll
        for (int i = 0; i < 4; i++) {
            int r   = r0 + jj + i;
            int c   = r >> 13;       // / (64*128)
            int rem = r & 8191;
            int d   = rem >> 7;
            int h   = rem & 127;
            const float* src =
                z + ((size_t)((c * ZD + d + 2) * ZH + (h + 2))) * ZW
                  + 2 + lane * 4;
            float2 a0 = __ldcs((const float2*)src);
            float2 a1 = __ldcs((const float2*)(src + 2));
            v[i] = make_float4(a0.x, a0.y, a1.x, a1.y);
        }
        #pragma unroll
        for (int i = 0; i < 4; i++) {
            int r   = r0 + jj + i;
            int c   = r >> 13;
            int rem = r & 8191;
            int d   = rem >> 7;
            int h   = rem & 127;
            float* dst = out + (size_t)(64 + c) * O_CH_STRIDE
                             + (size_t)d * (OH * OW) + h * OW + lane * 4;
            __stcs((float4*)dst, v[i]);
        }
    }
}

__global__ __launch_bounds__(256)
void upconv_cropcat_kernel(const float* __restrict__ x,
                           const float* __restrict__ z,
                           const float* __restrict__ W,
                           const float* __restrict__ b,
                           float* __restrict__ out)
{
    // 25 KB static smem -> 8 CTAs/SM (thread-cap occupancy)
    __shared__ float xs[64 * 32];     // [c][w'] half-plane tile, 8 KB
    __shared__ float Ws[64 * 65];     // [o][c] padded (conflict-free), 16.25 KB
    __shared__ float bs[64];

    const int bid  = blockIdx.x;
    const int tid  = threadIdx.x;
    const int warp = tid >> 5;
    const int lane = tid & 31;

    // ---- Phase 0: issue smem staging (latency overlapped by copy phase 1) ----
    const int dp   = bid >> 7;        // 0..31
    const int hp   = (bid >> 1) & 63; // 0..63
    const int half = bid & 1;         // w' offset 0 or 32

    // Stage W (4096 floats) via float4 loads into padded rows.
    const float4* __restrict__ W4 = (const float4*)W;
    #pragma unroll
    for (int i = tid; i < 1024; i += 256) {
        float4 v = W4[i];
        int o  = i >> 4;
        int c4 = (i & 15) << 2;
        float* dst = &Ws[o * 65 + c4];
        dst[0] = v.x; dst[1] = v.y; dst[2] = v.z; dst[3] = v.w;
    }
    // Stage x tile: 64 channels x 32 w' (contiguous per channel).
    const float* __restrict__ xbase =
        x + dp * (XH * XW) + hp * XW + half * 32;
    float4* xs4 = (float4*)xs;
    {
        int i = tid;             // 512 float4 over 256 threads, 2 each
        int c  = i >> 3, w4 = i & 7;
        xs4[i] = *(const float4*)(xbase + (size_t)c * X_CH_STRIDE + w4 * 4);
        i += 256; c = i >> 3; w4 = i & 7;
        xs4[i] = *(const float4*)(xbase + (size_t)c * X_CH_STRIDE + w4 * 4);
    }
    if (tid < 64) bs[tid] = b[tid];

    // ---- Phase 1: first copy half (8 rows per warp) ----
    const int r0 = bid * 128 + warp * 16;   // 4096 blocks * 128 rows = 524288
    copy_rows(z, out, r0, lane);

    __syncthreads();

    // ---- Phase 2: conv compute ----
    // Each thread: 2 output channels x 4 small-w values.
    const int wo = tid & 7;    // w-quad: w' = half*32 + wo*4 .. +3
    const int oo = tid >> 3;   // o-pair: o = oo*2, oo*2+1

    float acc[2][4];
    #pragma unroll
    for (int j = 0; j < 2; j++)
        #pragma unroll
        for (int k = 0; k < 4; k++)
            acc[j][k] = 0.0f;

    const float4* __restrict__ xcol = (const float4*)xs + wo;
    #pragma unroll 8
    for (int c = 0; c < 64; c++) {
        float4 xv = xcol[c * 8];
        #pragma unroll
        for (int j = 0; j < 2; j++) {
            float wv = Ws[(oo * 2 + j) * 65 + c];
            acc[j][0] = fmaf(wv, xv.x, acc[j][0]);
            acc[j][1] = fmaf(wv, xv.y, acc[j][1]);
            acc[j][2] = fmaf(wv, xv.z, acc[j][2]);
            acc[j][3] = fmaf(wv, xv.w, acc[j][3]);
        }
    }

    // Epilogue: duplicate each value 2x along w, write 4 output rows (2d x 2h).
    #pragma unroll
    for (int j = 0; j < 2; j++) {
        const int o = oo * 2 + j;
        const float bb = bs[o];
        float4 lo = make_float4(acc[j][0] + bb, acc[j][0] + bb,
                                acc[j][1] + bb, acc[j][1] + bb);
        float4 hi = make_float4(acc[j][2] + bb, acc[j][2] + bb,
                                acc[j][3] + bb, acc[j][3] + bb);
        float* obase = out + (size_t)o * O_CH_STRIDE
                           + (size_t)(2 * dp) * (OH * OW)
                           + (2 * hp) * OW + half * 64 + wo * 8;
        #pragma unroll
        for (int dd = 0; dd < 2; dd++) {
            #pragma unroll
            for (int hh = 0; hh < 2; hh++) {
                float* p = obase + dd * (OH * OW) + hh * OW;
                __stcs((float4*)p,     lo);
                __stcs((float4*)(p+4), hi);
            }
        }
    }

    // ---- Phase 3: second copy half (8 rows per warp) ----
    copy_rows(z, out, r0 + 8, lane);
}

extern "C" void kernel_launch(void* const* d_in, const int* in_sizes, int n_in,
                              void* d_out, int out_size)
{
    const float* x = (const float*)d_in[0];   // (1,64,32,64,64)
    const float* z = (const float*)d_in[1];   // (1,64,68,132,132)
    const float* W = (const float*)d_in[2];   // (64,64)
    const float* b = (const float*)d_in[3];   // (64,)
    float* out = (float*)d_out;               // (1,128,64,128,128)

    upconv_cropcat_kernel<<<NUM_BLOCKS, 256>>>(x, z, W, b, out);
}